// round 6
// baseline (speedup 1.0000x reference)
#include <cuda_runtime.h>
#include <stdint.h>

#define BATCH 16
#define H 128
#define W 128
#define HW (H*W)
#define CF 192
#define H2 64
#define W2 64

// per (batch, slot): [0..63] = source row indices, [64..127] = source col indices
__device__ int g_maps[BATCH][3][128];

// find with path-halving via PLAIN stores (no atomics). Safe: every written
// value is a valid ancestor; unions only modify roots via atomicMin.
__device__ __forceinline__ int find_pc(int* L, int x){
    volatile int* Lv = (volatile int*)L;
    int p = Lv[x];
    if (p == x) return x;
    for (;;){
        int gp = Lv[p];
        if (gp == p) return p;
        Lv[x] = gp;       // halve (benign race)
        x = p; p = gp;
    }
}

// lock-free union: link larger root under smaller via atomicMin
__device__ __forceinline__ void unite(int* L, int a, int b){
    a = find_pc(L, a);
    b = find_pc(L, b);
    while (a != b){
        if (a < b){ int t = a; a = b; b = t; }
        int old = atomicMin(&L[a], b);
        if (old == a) break;
        int hi = old > b ? old : b;
        int lo = old > b ? b : old;
        a = hi; b = lo;
    }
}

__device__ __forceinline__ void ins3(unsigned long long &k0, unsigned long long &k1,
                                     unsigned long long &k2, unsigned long long x){
    if (x > k0){ k2 = k1; k1 = k0; k0 = x; }
    else if (x > k1){ k2 = k1; k1 = x; }
    else if (x > k2){ k2 = x; }
}

__global__ void __launch_bounds__(1024, 1) ccl_kernel(const float* __restrict__ prob){
    extern __shared__ int smem[];
    int*   L      = smem;                     // HW ints
    int*   s_cnt  = smem + HW;                // HW ints
    float* s_conf = (float*)(smem + 2*HW);    // HW floats

    __shared__ unsigned s_mask[HW/32];        // 2KB foreground bitmask
    __shared__ unsigned long long s_r0[32], s_r1[32], s_r2[32];
    __shared__ int sK;
    __shared__ int s_slots[3];
    __shared__ int s_box[3][4];
    __shared__ float s_pcache;                // (unused, keeps layout simple)

    const int b    = blockIdx.x;
    const int tid  = threadIdx.x;
    const int lane = tid & 31;
    const int w    = tid >> 5;                // warp = strip of 4 rows
    const float* pb = prob + (size_t)b * HW;

    // =========== Phase A (warp-local, barrier-free) ===========
    // rows 4w..4w+3; masks in registers via ballot; labels via clz; zero stats.
    unsigned mw[4][4];
    const int base = w * (4 * W);             // pixel index of strip row 0, col 0
    #pragma unroll
    for (int rr = 0; rr < 4; rr++){
        #pragma unroll
        for (int k = 0; k < 4; k++){
            float p = __ldg(&pb[base + rr*W + k*32 + lane]);
            mw[rr][k] = __ballot_sync(0xffffffffu, p > 0.5f);
        }
        if (lane < 4){
            unsigned v = lane == 0 ? mw[rr][0] : lane == 1 ? mw[rr][1]
                       : lane == 2 ? mw[rr][2] : mw[rr][3];
            s_mask[(base + rr*W) / 32 + lane] = v;
        }
    }
    #pragma unroll
    for (int rr = 0; rr < 4; rr++){
        int rowpix = base + rr*W;
        #pragma unroll
        for (int k = 0; k < 4; k++){
            int i = rowpix + k*32 + lane;
            int v = -1;
            if ((mw[rr][k] >> lane) & 1u){
                unsigned lowm  = lane ? ((1u << lane) - 1u) : 0u;
                unsigned zeros = ~mw[rr][k] & lowm;
                int start;
                if (zeros) start = k*32 + (32 - __clz(zeros));
                else {
                    start = 0;
                    #pragma unroll
                    for (int j = k - 1; j >= 0; j--){
                        unsigned z = ~mw[rr][j];
                        if (z){ start = j*32 + (32 - __clz(z)); break; }
                    }
                }
                v = rowpix + start;
            }
            L[i] = v;
            s_cnt[i]  = 0;
            s_conf[i] = 0.f;
        }
    }
    if (tid == 0) sK = 0;
    if (tid < 12){
        int j = tid >> 2, q = tid & 3;
        s_box[j][q] = (q == 0 || q == 2) ? 0x7fffffff : -1;
    }
    __syncthreads();

    // =========== Phase B: single concurrent union pass ===========
    // warp w handles vertical edges into rows 4w..4w+3 (up-neighbor row).
    {
        unsigned mus[4];   // mask of row above (for rr==0 boundary)
        if (w > 0){
            int aw = 4*w - 1;
            #pragma unroll
            for (int k = 0; k < 4; k++) mus[k] = s_mask[aw*4 + k];
        }
        #pragma unroll
        for (int rr = 0; rr < 4; rr++){
            if (w == 0 && rr == 0) continue;
            int rowpix = base + rr*W;
            #pragma unroll
            for (int k = 0; k < 4; k++){
                unsigned cur = mw[rr][k];
                if (!cur) continue;
                unsigned up  = (rr > 0) ? mw[rr-1][k] : mus[k];
                unsigned upm1 = (k > 0) ? ((rr > 0) ? mw[rr-1][k-1] : mus[k-1]) : 0u;
                unsigned upp1 = (k < 3) ? ((rr > 0) ? mw[rr-1][k+1] : mus[k+1]) : 0u;
                unsigned curm1 = (k > 0) ? mw[rr][k-1] : 0u;
                unsigned curp1 = (k < 3) ? mw[rr][k+1] : 0u;
                unsigned Lc = (cur << 1) | (curm1 >> 31);   // left neighbor bits
                unsigned Rc = (cur >> 1) | (curp1 << 31);   // right neighbor bits
                unsigned Lu = (up  << 1) | (upm1  >> 31);   // up-left bits
                unsigned Ru = (up  >> 1) | (upp1  << 31);   // up-right bits

                if (!((cur >> lane) & 1u)) continue;
                int i = rowpix + k*32 + lane;
                bool lft = (Lc >> lane) & 1u;
                if ((up >> lane) & 1u){
                    bool upl = (Lu >> lane) & 1u;
                    if (!(lft && upl)) unite(L, i, i - W);
                } else {
                    bool upl = (Lu >> lane) & 1u;
                    bool upr = (Ru >> lane) & 1u;
                    bool rgt = (Rc >> lane) & 1u;
                    if (upl && !lft) unite(L, i, i - W - 1);
                    if (upr && !rgt) unite(L, i, i - W + 1);
                }
            }
        }
    }
    __syncthreads();

    // =========== single flatten pass ===========
    // No unions in flight: roots are stable; any concurrent write observed
    // mid-walk is a valid ancestor of the same component.
    for (int i = tid; i < HW; i += 1024){
        int p = L[i];
        if (p >= 0){
            int gp = L[p];
            while (gp != p){ p = gp; gp = L[p]; }
            L[i] = p;
        }
    }
    __syncthreads();

    // =========== per-component count & conf-sum ===========
    for (int i = tid; i < HW; i += 1024){
        int root = L[i];
        float p = (root >= 0) ? __ldg(&pb[i]) : 0.f;
        unsigned grp = __match_any_sync(0xffffffffu, root);
        float s = 0.f;
        unsigned m = grp;
        while (m){
            int l = __ffs(m) - 1;
            s += __shfl_sync(grp, p, l);
            m &= m - 1;
        }
        if (root >= 0 && lane == (__ffs(grp) - 1)){
            atomicAdd(&s_cnt[root],  __popc(grp));
            atomicAdd(&s_conf[root], s);
        }
    }
    __syncthreads();

    // =========== top-3 by mean confidence + K ===========
    unsigned long long k0 = 0, k1 = 0, k2 = 0;
    int localK = 0;
    for (int i = tid; i < HW; i += 1024){
        int cnt = s_cnt[i];
        if (cnt > 0){
            localK++;
            float mean = s_conf[i] / (float)cnt;       // in (0.5,1] => bit-monotone
            unsigned long long key =
                ((unsigned long long)__float_as_uint(mean) << 32) | (unsigned)(HW - 1 - i);
            ins3(k0, k1, k2, key);
        }
    }
    atomicAdd(&sK, localK);
    #pragma unroll
    for (int off = 16; off; off >>= 1){
        unsigned long long o0 = __shfl_down_sync(0xffffffffu, k0, off);
        unsigned long long o1 = __shfl_down_sync(0xffffffffu, k1, off);
        unsigned long long o2 = __shfl_down_sync(0xffffffffu, k2, off);
        ins3(k0, k1, k2, o0); ins3(k0, k1, k2, o1); ins3(k0, k1, k2, o2);
    }
    if (lane == 0){ s_r0[w] = k0; s_r1[w] = k1; s_r2[w] = k2; }
    __syncthreads();
    if (tid < 32){
        k0 = s_r0[tid]; k1 = s_r1[tid]; k2 = s_r2[tid];
        #pragma unroll
        for (int off = 16; off; off >>= 1){
            unsigned long long o0 = __shfl_down_sync(0xffffffffu, k0, off);
            unsigned long long o1 = __shfl_down_sync(0xffffffffu, k1, off);
            unsigned long long o2 = __shfl_down_sync(0xffffffffu, k2, off);
            ins3(k0, k1, k2, o0); ins3(k0, k1, k2, o1); ins3(k0, k1, k2, o2);
        }
        if (tid == 0){
            int K  = sK;
            int s0 = (HW - 1) - (int)(unsigned)(k0 & 0xffffffffull);
            int s1 = (HW - 1) - (int)(unsigned)(k1 & 0xffffffffull);
            int s2 = (HW - 1) - (int)(unsigned)(k2 & 0xffffffffull);
            int a0, a1, a2;
            if (K >= 3)      { a0 = s0; a1 = s1; a2 = s2; }
            else if (K == 2) { a0 = s0; a1 = s0; a2 = s1; }
            else             { a0 = s0; a1 = s0; a2 = s0; }
            s_slots[0] = a0; s_slots[1] = a1; s_slots[2] = a2;
        }
    }
    __syncthreads();

    // =========== bbox scan for the <=3 selected components ===========
    if (sK > 0){
        for (int i = tid; i < HW; i += 1024){
            int root = L[i];
            int r = i >> 7, c = i & (W - 1);
            #pragma unroll
            for (int j = 0; j < 3; j++){
                bool mt = (root >= 0) && (root == s_slots[j]);
                unsigned bal = __ballot_sync(0xffffffffu, mt);
                if (mt){
                    unsigned mnr = __reduce_min_sync(bal, (unsigned)r);
                    unsigned mxr = __reduce_max_sync(bal, (unsigned)r);
                    unsigned mnc = __reduce_min_sync(bal, (unsigned)c);
                    unsigned mxc = __reduce_max_sync(bal, (unsigned)c);
                    if (lane == (__ffs(bal) - 1)){
                        atomicMin(&s_box[j][0], (int)mnr);
                        atomicMax(&s_box[j][1], (int)mxr);
                        atomicMin(&s_box[j][2], (int)mnc);
                        atomicMax(&s_box[j][3], (int)mxc);
                    }
                }
            }
        }
    }
    __syncthreads();

    // =========== emit nearest-interp index maps ===========
    if (tid < 384){
        int j = tid >> 7, q = tid & 127;
        int mr, Mr, mc, Mc;
        if (sK == 0){ mr = 0; Mr = H; mc = 0; Mc = W; }
        else {
            mr = s_box[j][0]; Mr = s_box[j][1] + 1;
            mc = s_box[j][2]; Mc = s_box[j][3] + 1;
        }
        int v;
        if (q < 64) v = mr + ((q * (Mr - mr)) >> 6);
        else        { int x = q - 64; v = mc + ((x * (Mc - mc)) >> 6); }
        g_maps[b][j][q] = v;
    }
}

__global__ void __launch_bounds__(256) gather_kernel(const float* __restrict__ feat,
                                                     float* __restrict__ out){
    __shared__ int sm[128];
    int bid  = blockIdx.x;
    int slot = bid % 3;                 // 3 crops of same plane adjacent (L2 reuse)
    int rem  = bid / 3;
    int c    = rem % CF;
    int b    = rem / CF;

    if (threadIdx.x < 128) sm[threadIdx.x] = g_maps[b][slot][threadIdx.x];
    __syncthreads();
    const int* rmap = sm;
    const int* cmap = sm + 64;

    const float* src = feat + ((size_t)(b * CF + c)) * HW;
    float4* dst = (float4*)(out + ((size_t)b * (3 * CF) + (size_t)slot * CF + c) * (H2 * W2));

    #pragma unroll
    for (int i = threadIdx.x; i < (H2 * W2) / 4; i += 256){
        int y  = i >> 4;
        int x4 = (i & 15) << 2;
        const float* row = src + rmap[y] * W;
        float4 v;
        v.x = __ldg(&row[cmap[x4 + 0]]);
        v.y = __ldg(&row[cmap[x4 + 1]]);
        v.z = __ldg(&row[cmap[x4 + 2]]);
        v.w = __ldg(&row[cmap[x4 + 3]]);
        __stcs(&dst[i], v);   // streaming store: 151MB output, no reuse
    }
}

extern "C" void kernel_launch(void* const* d_in, const int* in_sizes, int n_in,
                              void* d_out, int out_size){
    const float* prob = (const float*)d_in[0];
    const float* feat = (const float*)d_in[1];
    if (in_sizes[0] != BATCH * HW){
        const float* t = prob; prob = feat; feat = t;
    }
    const int smem_bytes = 3 * HW * 4;   // 192KB
    cudaFuncSetAttribute(ccl_kernel, cudaFuncAttributeMaxDynamicSharedMemorySize, smem_bytes);

    ccl_kernel<<<BATCH, 1024, smem_bytes>>>(prob);
    gather_kernel<<<BATCH * 3 * CF, 256>>>(feat, (float*)d_out);
}